// round 8
// baseline (speedup 1.0000x reference)
#include <cuda_runtime.h>
#include <cuda_bf16.h>
#include <math.h>
#include <stdint.h>

// Problem constants
#define N_EMB   8192
#define D       512
#define P_MAX   4096
#define NEG_MAX 16384
#define INV_T   (1.0f / 0.07f)

// LSE GEMM: BM=128, BN=128, BK=64, 8 warps (4m x 2n), warp tile 32x64
#define BM 128
#define BN 128
#define BK 64
#define NSPLIT 8
#define CHUNKS 8                    // per CTA: 8 chunks x 128 = 1024 cols
#define SLABS  (CHUNKS * (D / BK))  // 64
#define NPART  NSPLIT

#define A_STAGE (BM * BK * 2)
#define B_STAGE (BN * BK * 2)
#define NSTAGE  3
#define SMEM_DYN (NSTAGE * (A_STAGE + B_STAGE))   // 98304

// Scratch (device globals: allocation is forbidden)
__device__ float         g_e [N_EMB * D];
__device__ __nv_bfloat16 g_eb[N_EMB * D];
__device__ float g_pm[NPART * P_MAX];
__device__ float g_ps[NPART * P_MAX];
__device__ float g_posdot [P_MAX];
__device__ float g_negdot [NEG_MAX];
__device__ float g_part_l[32];
__device__ float g_part_p[32];
__device__ float g_part_n[32];
// anchor dedup
__device__ int g_flag[N_EMB];
__device__ int g_list[N_EMB];
__device__ int g_inv [N_EMB];
__device__ int g_cnt;

// ---------------------------------------------------------------------------
__global__ void k_normalize(const float* __restrict__ emb) {
    int row = blockIdx.x;
    int t = threadIdx.x;
    if (t == 0) {
        g_flag[row] = 0;             // zero dedup flags (one per row-block)
        if (row == 0) g_cnt = 0;
    }
    const float4* src = (const float4*)emb + row * (D / 4);
    float4 v = src[t];
    float ss = v.x * v.x + v.y * v.y + v.z * v.z + v.w * v.w;
#pragma unroll
    for (int o = 16; o; o >>= 1) ss += __shfl_xor_sync(0xffffffffu, ss, o);
    __shared__ float red[4];
    if ((t & 31) == 0) red[t >> 5] = ss;
    __syncthreads();
    float tot = red[0] + red[1] + red[2] + red[3];
    float inv = 1.0f / fmaxf(sqrtf(tot), 1e-8f);
    v.x *= inv; v.y *= inv; v.z *= inv; v.w *= inv;
    ((float4*)g_e)[row * (D / 4) + t] = v;
    __nv_bfloat162 b0 = __floats2bfloat162_rn(v.x, v.y);
    __nv_bfloat162 b1 = __floats2bfloat162_rn(v.z, v.w);
    ((__nv_bfloat162*)g_eb)[row * (D / 2) + t * 2 + 0] = b0;
    ((__nv_bfloat162*)g_eb)[row * (D / 2) + t * 2 + 1] = b1;
}

// ---------------------------------------------------------------------------
// Pair dots (fp32, exact) + anchor-flag scatter for dedup.
__global__ void k_pairdot(const int* __restrict__ pa, const int* __restrict__ pt,
                          const int* __restrict__ na, const int* __restrict__ nt,
                          int nPos, int nNeg) {
    int warp = (blockIdx.x * blockDim.x + threadIdx.x) >> 5;
    int lane = threadIdx.x & 31;
    if (warp >= nPos + nNeg) return;
    int a, b;
    float* outp;
    if (warp < nPos) {
        a = pa[warp]; b = pt[warp]; outp = &g_posdot[warp];
        if (lane == 0) g_flag[a] = 1;
    } else {
        int w = warp - nPos;
        a = na[w]; b = nt[w]; outp = &g_negdot[w];
    }
    const float4* va = (const float4*)(g_e + (size_t)a * D);
    const float4* vb = (const float4*)(g_e + (size_t)b * D);
    float s = 0.0f;
#pragma unroll 4
    for (int i = lane; i < D / 4; i += 32) {
        float4 x = va[i];
        float4 y = vb[i];
        s += x.x * y.x + x.y * y.y + x.z * y.z + x.w * y.w;
    }
#pragma unroll
    for (int o = 16; o; o >>= 1) s += __shfl_xor_sync(0xffffffffu, s, o);
    if (lane == 0) *outp = s;
}

// ---------------------------------------------------------------------------
// Compact distinct anchor rows. Slot order is nondeterministic but outputs
// are slot-invariant (per-row LSE + fixed-order final sums).
__global__ void k_compact() {
    int i = blockIdx.x * blockDim.x + threadIdx.x;
    if (i >= N_EMB) return;
    if (g_flag[i]) {
        int slot = atomicAdd(&g_cnt, 1);
        g_list[slot] = i;
        g_inv[i] = slot;
    }
}

// ---------------------------------------------------------------------------
__device__ __forceinline__ void ldmatrix_x4(uint32_t* d, uint32_t addr) {
    asm volatile("ldmatrix.sync.aligned.m8n8.x4.shared.b16 {%0,%1,%2,%3}, [%4];"
                 : "=r"(d[0]), "=r"(d[1]), "=r"(d[2]), "=r"(d[3]) : "r"(addr));
}
__device__ __forceinline__ void mma16816(float* c, const uint32_t* a,
                                         uint32_t b0, uint32_t b1) {
    asm volatile("mma.sync.aligned.m16n8k16.row.col.f32.bf16.bf16.f32 "
                 "{%0,%1,%2,%3}, {%4,%5,%6,%7}, {%8,%9}, {%0,%1,%2,%3};"
                 : "+f"(c[0]), "+f"(c[1]), "+f"(c[2]), "+f"(c[3])
                 : "r"(a[0]), "r"(a[1]), "r"(a[2]), "r"(a[3]), "r"(b0), "r"(b1));
}
__device__ __forceinline__ uint32_t smem_u32(const void* p) {
    uint32_t a;
    asm("{ .reg .u64 t; cvta.to.shared.u64 t, %1; cvt.u32.u64 %0, t; }"
        : "=r"(a) : "l"(p));
    return a;
}
__device__ __forceinline__ void cp_async16(uint32_t smem_addr, const void* gptr) {
    asm volatile("cp.async.cg.shared.global [%0], [%1], 16;"
                 :: "r"(smem_addr), "l"(gptr));
}
__device__ __forceinline__ void cp_commit() {
    asm volatile("cp.async.commit_group;");
}
template <int N>
__device__ __forceinline__ void cp_wait() {
    asm volatile("cp.async.wait_group %0;" :: "n"(N) : "memory");
}

// ---------------------------------------------------------------------------
// Fused gathered bf16 MMA GEMM + online LSE over DISTINCT anchor rows.
__global__ __launch_bounds__(256, 2) void k_lse(int nPos) {
    int cnt = g_cnt;
    int m0 = blockIdx.x * BM;
    if (m0 >= cnt) return;

    extern __shared__ __align__(16) char dsm[];
    uint32_t a_base = smem_u32(dsm);
    uint32_t b_base = a_base + NSTAGE * A_STAGE;

    __shared__ int arow[BM];
    __shared__ float pm_s[2][BM];
    __shared__ float ps_s[2][BM];

    int tid = threadIdx.x;
    int warp = tid >> 5;
    int lane = tid & 31;
    int warpm = warp >> 1;
    int warpn = warp & 1;
    int n_base = blockIdx.y * (CHUNKS * BN);

    if (tid < BM) {
        int p = m0 + tid;
        if (p >= cnt) p = cnt - 1;
        arow[tid] = g_list[p];
    }
    __syncthreads();

    auto load_slab = [&](int t) {
        int c = t >> 3;
        int kp = t & 7;
        int k0 = kp * BK;
        int n0 = n_base + c * BN;
        uint32_t Ab = a_base + (t % NSTAGE) * A_STAGE;
        uint32_t Bb = b_base + (t % NSTAGE) * B_STAGE;
#pragma unroll
        for (int it = 0; it < 4; it++) {
            int id = it * 256 + tid;
            int r = id >> 3;
            int ci = id & 7;
            uint32_t off = ((uint32_t)r * 128u + (uint32_t)ci * 16u)
                         ^ ((uint32_t)(r & 7) << 4);
            cp_async16(Ab + off, g_eb + (size_t)arow[r] * D + k0 + ci * 8);
            cp_async16(Bb + off, g_eb + (size_t)(n0 + r) * D + k0 + ci * 8);
        }
        cp_commit();
    };

    float rmv[4];
    float rsv[4];
#pragma unroll
    for (int u = 0; u < 4; u++) { rmv[u] = -1e30f; rsv[u] = 0.0f; }

    float acc[64];
#pragma unroll
    for (int q = 0; q < 64; q++) acc[q] = 0.0f;

    load_slab(0);
    load_slab(1);

    for (int t = 0; t < SLABS; t++) {
        if (t < SLABS - 1) cp_wait<1>(); else cp_wait<0>();
        __syncthreads();
        if (t + 2 < SLABS) load_slab(t + 2);

        uint32_t Ab = a_base + (t % NSTAGE) * A_STAGE;
        uint32_t Bb = b_base + (t % NSTAGE) * B_STAGE;
#pragma unroll
        for (int kk = 0; kk < 4; kk++) {
            uint32_t afr0[4];
            uint32_t afr1[4];
            uint32_t bfr[4][4];
            {
                int r = warpm * 32 + (lane & 15);
                uint32_t off = ((uint32_t)r * 128u + (uint32_t)kk * 32u
                               + (uint32_t)(lane >> 4) * 16u)
                             ^ ((uint32_t)(r & 7) << 4);
                ldmatrix_x4(afr0, Ab + off);
            }
            {
                int r = warpm * 32 + 16 + (lane & 15);
                uint32_t off = ((uint32_t)r * 128u + (uint32_t)kk * 32u
                               + (uint32_t)(lane >> 4) * 16u)
                             ^ ((uint32_t)(r & 7) << 4);
                ldmatrix_x4(afr1, Ab + off);
            }
#pragma unroll
            for (int g = 0; g < 4; g++) {
                int r = warpn * 64 + g * 16 + (lane & 15);
                uint32_t off = ((uint32_t)r * 128u + (uint32_t)kk * 32u
                               + (uint32_t)(lane >> 4) * 16u)
                             ^ ((uint32_t)(r & 7) << 4);
                ldmatrix_x4(bfr[g], Bb + off);
            }
#pragma unroll
            for (int g = 0; g < 4; g++) {
                mma16816(&acc[(2 * g + 0) * 4], afr0, bfr[g][0], bfr[g][2]);
                mma16816(&acc[(2 * g + 1) * 4], afr0, bfr[g][1], bfr[g][3]);
                mma16816(&acc[(8 + 2 * g + 0) * 4], afr1, bfr[g][0], bfr[g][2]);
                mma16816(&acc[(8 + 2 * g + 1) * 4], afr1, bfr[g][1], bfr[g][3]);
            }
        }

        if ((t & 7) == 7) {
#pragma unroll
            for (int u = 0; u < 4; u++) {
                int mi = u >> 1;
                int h = u & 1;
                float vals[16];
#pragma unroll
                for (int j = 0; j < 8; j++) {
                    vals[2 * j + 0] = acc[(mi * 8 + j) * 4 + h * 2 + 0] * INV_T;
                    vals[2 * j + 1] = acc[(mi * 8 + j) * 4 + h * 2 + 1] * INV_T;
                }
                float vmax = vals[0];
#pragma unroll
                for (int q = 1; q < 16; q++) vmax = fmaxf(vmax, vals[q]);
                float vsum = 0.0f;
#pragma unroll
                for (int q = 0; q < 16; q++) vsum += __expf(vals[q] - vmax);
#pragma unroll
                for (int o = 1; o < 4; o <<= 1) {
                    float mo = __shfl_xor_sync(0xffffffffu, vmax, o);
                    float so = __shfl_xor_sync(0xffffffffu, vsum, o);
                    float nm = fmaxf(vmax, mo);
                    vsum = vsum * __expf(vmax - nm) + so * __expf(mo - nm);
                    vmax = nm;
                }
                if ((lane & 3) == 0) {
                    int lr = warpm * 32 + mi * 16 + h * 8 + (lane >> 2);
                    pm_s[warpn][lr] = vmax;
                    ps_s[warpn][lr] = vsum;
                }
            }
            __syncthreads();
            if (warpn == 0) {
#pragma unroll
                for (int u = 0; u < 4; u++) {
                    int mi = u >> 1;
                    int h = u & 1;
                    int lr = warpm * 32 + mi * 16 + h * 8 + (lane >> 2);
                    float m = pm_s[0][lr];
                    float s = ps_s[0][lr];
                    float mo = pm_s[1][lr];
                    float so = ps_s[1][lr];
                    float nm = fmaxf(m, mo);
                    s = s * __expf(m - nm) + so * __expf(mo - nm);
                    m = nm;
                    float nr = fmaxf(rmv[u], m);
                    rsv[u] = rsv[u] * __expf(rmv[u] - nr) + s * __expf(m - nr);
                    rmv[u] = nr;
                }
            }
            __syncthreads();
#pragma unroll
            for (int q = 0; q < 64; q++) acc[q] = 0.0f;
        }
    }

    if (warpn == 0 && (lane & 3) == 0) {
#pragma unroll
        for (int u = 0; u < 4; u++) {
            int mi = u >> 1;
            int h = u & 1;
            int slot = m0 + warpm * 32 + mi * 16 + h * 8 + (lane >> 2);
            if (slot < cnt) {
                g_pm[blockIdx.y * P_MAX + slot] = rmv[u];
                g_ps[blockIdx.y * P_MAX + slot] = rsv[u];
            }
        }
    }
}

// ---------------------------------------------------------------------------
// Finalize stage 1: blocks 0-31 pos pairs (LSE via dedup slot), 32-63 neg sums.
__global__ void k_fin1(const int* __restrict__ pa, int nPos, int nNeg) {
    int b = blockIdx.x;
    int t = threadIdx.x;
    __shared__ float r0[128];
    __shared__ float r1[128];
    if (b < 32) {
        int p = b * 128 + t;
        float lv = 0.0f;
        float pv = 0.0f;
        if (p < nPos) {
            int slot = g_inv[pa[p]];
            float m = -1e30f;
            float s = 0.0f;
#pragma unroll
            for (int k = 0; k < NPART; k++) {
                float mk = g_pm[k * P_MAX + slot];
                float sk = g_ps[k * P_MAX + slot];
                float nm = fmaxf(m, mk);
                s = s * __expf(m - nm) + sk * __expf(mk - nm);
                m = nm;
            }
            float d = g_posdot[p];
            lv = m + logf(s) - d * INV_T;
            pv = d;
        }
        r0[t] = lv;
        r1[t] = pv;
        __syncthreads();
        for (int o = 64; o; o >>= 1) {
            if (t < o) { r0[t] += r0[t + o]; r1[t] += r1[t + o]; }
            __syncthreads();
        }
        if (t == 0) { g_part_l[b] = r0[0]; g_part_p[b] = r1[0]; }
    } else {
        int nb = b - 32;
        float nv = 0.0f;
#pragma unroll
        for (int i = 0; i < 4; i++) {
            int idx = nb * 512 + i * 128 + t;
            if (idx < nNeg) nv += g_negdot[idx];
        }
        r0[t] = nv;
        __syncthreads();
        for (int o = 64; o; o >>= 1) {
            if (t < o) r0[t] += r0[t + o];
            __syncthreads();
        }
        if (t == 0) g_part_n[nb] = r0[0];
    }
}

// Finalize stage 2
__global__ void k_fin2(float* __restrict__ outp, int nPos, int nNeg, int out_size) {
    int t = threadIdx.x;
    float lv = (t < 32) ? g_part_l[t] : 0.0f;
    float pv = (t < 32) ? g_part_p[t] : 0.0f;
    float nv = (t < 32) ? g_part_n[t] : 0.0f;
#pragma unroll
    for (int o = 16; o; o >>= 1) {
        lv += __shfl_xor_sync(0xffffffffu, lv, o);
        pv += __shfl_xor_sync(0xffffffffu, pv, o);
        nv += __shfl_xor_sync(0xffffffffu, nv, o);
    }
    if (t == 0) {
        if (out_size > 0) outp[0] = lv / (float)nPos;
        if (out_size > 1) outp[1] = pv / (float)nPos;
        if (out_size > 2) outp[2] = nv / (float)nNeg;
    }
}

// ---------------------------------------------------------------------------
extern "C" void kernel_launch(void* const* d_in, const int* in_sizes, int n_in,
                              void* d_out, int out_size) {
    const float* emb = (const float*)d_in[0];
    const int* pa = (const int*)d_in[1];
    const int* pt = (const int*)d_in[2];
    const int* na = (const int*)d_in[3];
    const int* nt = (const int*)d_in[4];
    int nPos = in_sizes[1];
    int nNeg = in_sizes[3];

    cudaFuncSetAttribute(k_lse, cudaFuncAttributeMaxDynamicSharedMemorySize, SMEM_DYN);

    k_normalize<<<N_EMB, 128>>>(emb);

    int pairs = nPos + nNeg;
    int pblocks = (pairs * 32 + 255) / 256;
    k_pairdot<<<pblocks, 256>>>(pa, pt, na, nt, nPos, nNeg);

    k_compact<<<N_EMB / 256, 256>>>();

    dim3 grid((P_MAX + BM - 1) / BM, NSPLIT);
    k_lse<<<grid, 256, SMEM_DYN>>>(nPos);

    k_fin1<<<64, 128>>>(pa, nPos, nNeg);
    k_fin2<<<1, 32>>>((float*)d_out, nPos, nNeg, out_size);
}

// round 10
// speedup vs baseline: 1.2808x; 1.2808x over previous
#include <cuda_runtime.h>
#include <cuda_bf16.h>
#include <math.h>
#include <stdint.h>

// Problem constants
#define N_EMB   8192
#define D       512
#define P_MAX   4096
#define NEG_MAX 16384
#define INV_T   (1.0f / 0.07f)

// LSE GEMM: BM=128, BN=128, BK=64, 8 warps (4m x 2n), warp tile 32x64
#define BM 128
#define BN 128
#define BK 64
#define NSPLIT 11                   // 64 chunks split 9x6 + 2x5
#define NPART  NSPLIT

#define A_STAGE (BM * BK * 2)
#define B_STAGE (BN * BK * 2)
#define NSTAGE  3
#define SMEM_DYN (NSTAGE * (A_STAGE + B_STAGE))   // 98304

// Scratch (device globals: allocation is forbidden)
__device__ float         g_e [N_EMB * D];
__device__ __nv_bfloat16 g_eb[N_EMB * D];
__device__ float g_pm[NPART * P_MAX];
__device__ float g_ps[NPART * P_MAX];
__device__ float g_posdot [P_MAX];
__device__ float g_negdot [NEG_MAX];
__device__ float g_part_l[32];
__device__ float g_part_p[32];
__device__ float g_part_n[32];
// anchor dedup
__device__ int g_flag[N_EMB];
__device__ int g_list[N_EMB];
__device__ int g_inv [N_EMB];
__device__ int g_cnt;

// ---------------------------------------------------------------------------
__global__ void k_normalize(const float* __restrict__ emb) {
    int row = blockIdx.x;
    int t = threadIdx.x;
    if (t == 0) {
        g_flag[row] = 0;
        if (row == 0) g_cnt = 0;
    }
    const float4* src = (const float4*)emb + row * (D / 4);
    float4 v = src[t];
    float ss = v.x * v.x + v.y * v.y + v.z * v.z + v.w * v.w;
#pragma unroll
    for (int o = 16; o; o >>= 1) ss += __shfl_xor_sync(0xffffffffu, ss, o);
    __shared__ float red[4];
    if ((t & 31) == 0) red[t >> 5] = ss;
    __syncthreads();
    float tot = red[0] + red[1] + red[2] + red[3];
    float inv = 1.0f / fmaxf(sqrtf(tot), 1e-8f);
    v.x *= inv; v.y *= inv; v.z *= inv; v.w *= inv;
    ((float4*)g_e)[row * (D / 4) + t] = v;
    __nv_bfloat162 b0 = __floats2bfloat162_rn(v.x, v.y);
    __nv_bfloat162 b1 = __floats2bfloat162_rn(v.z, v.w);
    ((__nv_bfloat162*)g_eb)[row * (D / 2) + t * 2 + 0] = b0;
    ((__nv_bfloat162*)g_eb)[row * (D / 2) + t * 2 + 1] = b1;
}

// ---------------------------------------------------------------------------
__global__ void k_pairdot(const int* __restrict__ pa, const int* __restrict__ pt,
                          const int* __restrict__ na, const int* __restrict__ nt,
                          int nPos, int nNeg) {
    int warp = (blockIdx.x * blockDim.x + threadIdx.x) >> 5;
    int lane = threadIdx.x & 31;
    if (warp >= nPos + nNeg) return;
    int a, b;
    float* outp;
    if (warp < nPos) {
        a = pa[warp]; b = pt[warp]; outp = &g_posdot[warp];
        if (lane == 0) g_flag[a] = 1;
    } else {
        int w = warp - nPos;
        a = na[w]; b = nt[w]; outp = &g_negdot[w];
    }
    const float4* va = (const float4*)(g_e + (size_t)a * D);
    const float4* vb = (const float4*)(g_e + (size_t)b * D);
    float s = 0.0f;
#pragma unroll 4
    for (int i = lane; i < D / 4; i += 32) {
        float4 x = va[i];
        float4 y = vb[i];
        s += x.x * y.x + x.y * y.y + x.z * y.z + x.w * y.w;
    }
#pragma unroll
    for (int o = 16; o; o >>= 1) s += __shfl_xor_sync(0xffffffffu, s, o);
    if (lane == 0) *outp = s;
}

// ---------------------------------------------------------------------------
__global__ void k_compact() {
    int i = blockIdx.x * blockDim.x + threadIdx.x;
    if (i >= N_EMB) return;
    if (g_flag[i]) {
        int slot = atomicAdd(&g_cnt, 1);
        g_list[slot] = i;
        g_inv[i] = slot;
    }
}

// ---------------------------------------------------------------------------
__device__ __forceinline__ void ldmatrix_x4(uint32_t* d, uint32_t addr) {
    asm volatile("ldmatrix.sync.aligned.m8n8.x4.shared.b16 {%0,%1,%2,%3}, [%4];"
                 : "=r"(d[0]), "=r"(d[1]), "=r"(d[2]), "=r"(d[3]) : "r"(addr));
}
__device__ __forceinline__ void mma16816(float* c, const uint32_t* a,
                                         uint32_t b0, uint32_t b1) {
    asm volatile("mma.sync.aligned.m16n8k16.row.col.f32.bf16.bf16.f32 "
                 "{%0,%1,%2,%3}, {%4,%5,%6,%7}, {%8,%9}, {%0,%1,%2,%3};"
                 : "+f"(c[0]), "+f"(c[1]), "+f"(c[2]), "+f"(c[3])
                 : "r"(a[0]), "r"(a[1]), "r"(a[2]), "r"(a[3]), "r"(b0), "r"(b1));
}
__device__ __forceinline__ uint32_t smem_u32(const void* p) {
    uint32_t a;
    asm("{ .reg .u64 t; cvta.to.shared.u64 t, %1; cvt.u32.u64 %0, t; }"
        : "=r"(a) : "l"(p));
    return a;
}
__device__ __forceinline__ void cp_async16(uint32_t smem_addr, const void* gptr) {
    asm volatile("cp.async.cg.shared.global [%0], [%1], 16;"
                 :: "r"(smem_addr), "l"(gptr));
}
__device__ __forceinline__ void cp_commit() {
    asm volatile("cp.async.commit_group;");
}
template <int N>
__device__ __forceinline__ void cp_wait() {
    asm volatile("cp.async.wait_group %0;" :: "n"(N) : "memory");
}

// ---------------------------------------------------------------------------
// Fused gathered bf16 MMA GEMM + online LSE over distinct anchors.
// Ragged NSPLIT=11: each CTA covers 5-6 chunks (40-48 slabs) so the dedup'd
// grid (~283 CTAs) fills one 2-CTA/SM wave with a shorter critical path.
__global__ __launch_bounds__(256, 2) void k_lse(int nPos) {
    int cnt = g_cnt;
    int m0 = blockIdx.x * BM;
    if (m0 >= cnt) return;

    int y = blockIdx.y;
    int c_start = (y < 9) ? 6 * y : 54 + 5 * (y - 9);
    int c_cnt   = (y < 9) ? 6 : 5;
    int nslabs  = c_cnt * 8;

    extern __shared__ __align__(16) char dsm[];
    uint32_t a_base = smem_u32(dsm);
    uint32_t b_base = a_base + NSTAGE * A_STAGE;

    __shared__ int arow[BM];
    __shared__ float pm_s[2][BM];
    __shared__ float ps_s[2][BM];

    int tid = threadIdx.x;
    int warp = tid >> 5;
    int lane = tid & 31;
    int warpm = warp >> 1;
    int warpn = warp & 1;

    if (tid < BM) {
        int p = m0 + tid;
        if (p >= cnt) p = cnt - 1;
        arow[tid] = g_list[p];
    }
    __syncthreads();

    // Loader geometry (hoist is safe: XOR bits 4-6 keep value <4096; +it*4096
    // has disjoint bits, no carry interaction).
    int lr0 = tid >> 3;
    int lci = tid & 7;
    uint32_t dst0 = ((uint32_t)lr0 * 128u + (uint32_t)lci * 16u)
                  ^ ((uint32_t)(lr0 & 7) << 4);

    auto load_slab = [&](int t) {
        int c = c_start + (t >> 3);
        int kp = t & 7;
        int k0 = kp * BK;
        int n0 = c * BN;
        uint32_t Ab = a_base + (t % NSTAGE) * A_STAGE + dst0;
        uint32_t Bb = b_base + (t % NSTAGE) * B_STAGE + dst0;
        const __nv_bfloat16* bsrc = g_eb + (size_t)(n0 + lr0) * D + k0 + lci * 8;
#pragma unroll
        for (int it = 0; it < 4; it++) {
            cp_async16(Ab + it * 4096u,
                       g_eb + (size_t)arow[it * 32 + lr0] * D + k0 + lci * 8);
            cp_async16(Bb + it * 4096u, bsrc + (size_t)(it * 32) * D);
        }
        cp_commit();
    };

    // ldmatrix bases UN-swizzled; swizzle XOR applied AFTER adding kk offset
    // (XOR does not commute with ADD across the carry into bit 7).
    // row&7 == lane&7 for every fragment row here -> one swz register.
    uint32_t swz = ((uint32_t)(lane & 7)) << 4;
    uint32_t baseA0 = (uint32_t)(warpm * 32 + (lane & 15)) * 128u
                    + (uint32_t)(lane >> 4) * 16u;
    uint32_t baseA1 = baseA0 + 16u * 128u;
    uint32_t baseB0 = (uint32_t)(warpn * 64 + (lane & 15)) * 128u
                    + (uint32_t)(lane >> 4) * 16u;

    float rmv[4];
    float rsv[4];
#pragma unroll
    for (int u = 0; u < 4; u++) { rmv[u] = -1e30f; rsv[u] = 0.0f; }

    float acc[64];
#pragma unroll
    for (int q = 0; q < 64; q++) acc[q] = 0.0f;

    load_slab(0);
    load_slab(1);

    for (int t = 0; t < nslabs; t++) {
        if (t < nslabs - 1) cp_wait<1>(); else cp_wait<0>();
        __syncthreads();
        if (t + 2 < nslabs) load_slab(t + 2);

        uint32_t Ab = a_base + (t % NSTAGE) * A_STAGE;
        uint32_t Bb = b_base + (t % NSTAGE) * B_STAGE;
#pragma unroll
        for (int kk = 0; kk < 4; kk++) {
            uint32_t kof = (uint32_t)kk * 32u;
            uint32_t afr0[4];
            uint32_t afr1[4];
            uint32_t bfr[4][4];
            ldmatrix_x4(afr0, Ab + ((baseA0 + kof) ^ swz));
            ldmatrix_x4(afr1, Ab + ((baseA1 + kof) ^ swz));
#pragma unroll
            for (int g = 0; g < 4; g++)
                ldmatrix_x4(bfr[g], Bb + ((baseB0 + (uint32_t)g * 2048u + kof) ^ swz));
#pragma unroll
            for (int g = 0; g < 4; g++) {
                mma16816(&acc[(2 * g + 0) * 4], afr0, bfr[g][0], bfr[g][2]);
                mma16816(&acc[(2 * g + 1) * 4], afr0, bfr[g][1], bfr[g][3]);
                mma16816(&acc[(8 + 2 * g + 0) * 4], afr1, bfr[g][0], bfr[g][2]);
                mma16816(&acc[(8 + 2 * g + 1) * 4], afr1, bfr[g][1], bfr[g][3]);
            }
        }

        if ((t & 7) == 7) {
            // epilogue: online LSE over this 128-col chunk
#pragma unroll
            for (int u = 0; u < 4; u++) {
                int mi = u >> 1;
                int h = u & 1;
                float vals[16];
#pragma unroll
                for (int j = 0; j < 8; j++) {
                    vals[2 * j + 0] = acc[(mi * 8 + j) * 4 + h * 2 + 0] * INV_T;
                    vals[2 * j + 1] = acc[(mi * 8 + j) * 4 + h * 2 + 1] * INV_T;
                }
                float vmax = vals[0];
#pragma unroll
                for (int q = 1; q < 16; q++) vmax = fmaxf(vmax, vals[q]);
                float vsum = 0.0f;
#pragma unroll
                for (int q = 0; q < 16; q++) vsum += __expf(vals[q] - vmax);
#pragma unroll
                for (int o = 1; o < 4; o <<= 1) {
                    float mo = __shfl_xor_sync(0xffffffffu, vmax, o);
                    float so = __shfl_xor_sync(0xffffffffu, vsum, o);
                    float nm = fmaxf(vmax, mo);
                    vsum = vsum * __expf(vmax - nm) + so * __expf(mo - nm);
                    vmax = nm;
                }
                if ((lane & 3) == 0) {
                    int lrr = warpm * 32 + mi * 16 + h * 8 + (lane >> 2);
                    pm_s[warpn][lrr] = vmax;
                    ps_s[warpn][lrr] = vsum;
                }
            }
            __syncthreads();
            if (warpn == 0) {
#pragma unroll
                for (int u = 0; u < 4; u++) {
                    int mi = u >> 1;
                    int h = u & 1;
                    int lrr = warpm * 32 + mi * 16 + h * 8 + (lane >> 2);
                    float m = pm_s[0][lrr];
                    float s = ps_s[0][lrr];
                    float mo = pm_s[1][lrr];
                    float so = ps_s[1][lrr];
                    float nm = fmaxf(m, mo);
                    s = s * __expf(m - nm) + so * __expf(mo - nm);
                    m = nm;
                    float nr = fmaxf(rmv[u], m);
                    rsv[u] = rsv[u] * __expf(rmv[u] - nr) + s * __expf(m - nr);
                    rmv[u] = nr;
                }
            }
            __syncthreads();
#pragma unroll
            for (int q = 0; q < 64; q++) acc[q] = 0.0f;
        }
    }

    if (warpn == 0 && (lane & 3) == 0) {
#pragma unroll
        for (int u = 0; u < 4; u++) {
            int mi = u >> 1;
            int h = u & 1;
            int slot = m0 + warpm * 32 + mi * 16 + h * 8 + (lane >> 2);
            if (slot < cnt) {
                g_pm[y * P_MAX + slot] = rmv[u];
                g_ps[y * P_MAX + slot] = rsv[u];
            }
        }
    }
}

// ---------------------------------------------------------------------------
__global__ void k_fin1(const int* __restrict__ pa, int nPos, int nNeg) {
    int b = blockIdx.x;
    int t = threadIdx.x;
    __shared__ float r0[128];
    __shared__ float r1[128];
    if (b < 32) {
        int p = b * 128 + t;
        float lv = 0.0f;
        float pv = 0.0f;
        if (p < nPos) {
            int slot = g_inv[pa[p]];
            float m = -1e30f;
            float s = 0.0f;
#pragma unroll
            for (int k = 0; k < NPART; k++) {
                float mk = g_pm[k * P_MAX + slot];
                float sk = g_ps[k * P_MAX + slot];
                float nm = fmaxf(m, mk);
                s = s * __expf(m - nm) + sk * __expf(mk - nm);
                m = nm;
            }
            float d = g_posdot[p];
            lv = m + logf(s) - d * INV_T;
            pv = d;
        }
        r0[t] = lv;
        r1[t] = pv;
        __syncthreads();
        for (int o = 64; o; o >>= 1) {
            if (t < o) { r0[t] += r0[t + o]; r1[t] += r1[t + o]; }
            __syncthreads();
        }
        if (t == 0) { g_part_l[b] = r0[0]; g_part_p[b] = r1[0]; }
    } else {
        int nb = b - 32;
        float nv = 0.0f;
#pragma unroll
        for (int i = 0; i < 4; i++) {
            int idx = nb * 512 + i * 128 + t;
            if (idx < nNeg) nv += g_negdot[idx];
        }
        r0[t] = nv;
        __syncthreads();
        for (int o = 64; o; o >>= 1) {
            if (t < o) r0[t] += r0[t + o];
            __syncthreads();
        }
        if (t == 0) g_part_n[nb] = r0[0];
    }
}

__global__ void k_fin2(float* __restrict__ outp, int nPos, int nNeg, int out_size) {
    int t = threadIdx.x;
    float lv = (t < 32) ? g_part_l[t] : 0.0f;
    float pv = (t < 32) ? g_part_p[t] : 0.0f;
    float nv = (t < 32) ? g_part_n[t] : 0.0f;
#pragma unroll
    for (int o = 16; o; o >>= 1) {
        lv += __shfl_xor_sync(0xffffffffu, lv, o);
        pv += __shfl_xor_sync(0xffffffffu, pv, o);
        nv += __shfl_xor_sync(0xffffffffu, nv, o);
    }
    if (t == 0) {
        if (out_size > 0) outp[0] = lv / (float)nPos;
        if (out_size > 1) outp[1] = pv / (float)nPos;
        if (out_size > 2) outp[2] = nv / (float)nNeg;
    }
}

// ---------------------------------------------------------------------------
extern "C" void kernel_launch(void* const* d_in, const int* in_sizes, int n_in,
                              void* d_out, int out_size) {
    const float* emb = (const float*)d_in[0];
    const int* pa = (const int*)d_in[1];
    const int* pt = (const int*)d_in[2];
    const int* na = (const int*)d_in[3];
    const int* nt = (const int*)d_in[4];
    int nPos = in_sizes[1];
    int nNeg = in_sizes[3];

    cudaFuncSetAttribute(k_lse, cudaFuncAttributeMaxDynamicSharedMemorySize, SMEM_DYN);

    k_normalize<<<N_EMB, 128>>>(emb);

    int pairs = nPos + nNeg;
    int pblocks = (pairs * 32 + 255) / 256;
    k_pairdot<<<pblocks, 256>>>(pa, pt, na, nt, nPos, nNeg);

    k_compact<<<N_EMB / 256, 256>>>();

    dim3 grid((P_MAX + BM - 1) / BM, NSPLIT);
    k_lse<<<grid, 256, SMEM_DYN>>>(nPos);

    k_fin1<<<64, 128>>>(pa, nPos, nNeg);
    k_fin2<<<1, 32>>>((float*)d_out, nPos, nNeg, out_size);
}

// round 11
// speedup vs baseline: 1.3258x; 1.0351x over previous
#include <cuda_runtime.h>
#include <cuda_bf16.h>
#include <cuda_fp16.h>
#include <math.h>
#include <stdint.h>

// Problem constants
#define N_EMB   8192
#define D       512
#define P_MAX   4096
#define NEG_MAX 16384
#define INV_T   (1.0f / 0.07f)

// LSE GEMM: BM=128, BN=128, BK=64, 8 warps (4m x 2n), warp tile 32x64
#define BM 128
#define BN 128
#define BK 64
#define NSPLIT 11                   // 64 chunks split 9x6 + 2x5
#define NPART  NSPLIT

#define A_STAGE (BM * BK * 2)
#define B_STAGE (BN * BK * 2)
#define NSTAGE  3
#define SMEM_DYN (NSTAGE * (A_STAGE + B_STAGE))   // 98304

// Scratch (device globals: allocation is forbidden)
__device__ float  g_e [N_EMB * D];
__device__ __half g_eh[N_EMB * D];
__device__ float g_pm[NPART * P_MAX];
__device__ float g_ps[NPART * P_MAX];
__device__ float g_posdot [P_MAX];
__device__ float g_negdot [NEG_MAX];
__device__ float g_part_l[32];
__device__ float g_part_p[32];
__device__ float g_part_n[32];
// anchor dedup
__device__ int g_flag[N_EMB];
__device__ int g_list[N_EMB];
__device__ int g_inv [N_EMB];
__device__ int g_cnt;

// ---------------------------------------------------------------------------
__global__ void k_normalize(const float* __restrict__ emb) {
    int row = blockIdx.x;
    int t = threadIdx.x;
    if (t == 0) {
        g_flag[row] = 0;
        if (row == 0) g_cnt = 0;
    }
    const float4* src = (const float4*)emb + row * (D / 4);
    float4 v = src[t];
    float ss = v.x * v.x + v.y * v.y + v.z * v.z + v.w * v.w;
#pragma unroll
    for (int o = 16; o; o >>= 1) ss += __shfl_xor_sync(0xffffffffu, ss, o);
    __shared__ float red[4];
    if ((t & 31) == 0) red[t >> 5] = ss;
    __syncthreads();
    float tot = red[0] + red[1] + red[2] + red[3];
    float inv = 1.0f / fmaxf(sqrtf(tot), 1e-8f);
    v.x *= inv; v.y *= inv; v.z *= inv; v.w *= inv;
    ((float4*)g_e)[row * (D / 4) + t] = v;
    __half2 h0 = __floats2half2_rn(v.x, v.y);
    __half2 h1 = __floats2half2_rn(v.z, v.w);
    ((__half2*)g_eh)[row * (D / 2) + t * 2 + 0] = h0;
    ((__half2*)g_eh)[row * (D / 2) + t * 2 + 1] = h1;
}

// ---------------------------------------------------------------------------
__global__ void k_pairdot(const int* __restrict__ pa, const int* __restrict__ pt,
                          const int* __restrict__ na, const int* __restrict__ nt,
                          int nPos, int nNeg) {
    int warp = (blockIdx.x * blockDim.x + threadIdx.x) >> 5;
    int lane = threadIdx.x & 31;
    if (warp >= nPos + nNeg) return;
    int a, b;
    float* outp;
    if (warp < nPos) {
        a = pa[warp]; b = pt[warp]; outp = &g_posdot[warp];
        if (lane == 0) g_flag[a] = 1;
    } else {
        int w = warp - nPos;
        a = na[w]; b = nt[w]; outp = &g_negdot[w];
    }
    const float4* va = (const float4*)(g_e + (size_t)a * D);
    const float4* vb = (const float4*)(g_e + (size_t)b * D);
    float s = 0.0f;
#pragma unroll 4
    for (int i = lane; i < D / 4; i += 32) {
        float4 x = va[i];
        float4 y = vb[i];
        s += x.x * y.x + x.y * y.y + x.z * y.z + x.w * y.w;
    }
#pragma unroll
    for (int o = 16; o; o >>= 1) s += __shfl_xor_sync(0xffffffffu, s, o);
    if (lane == 0) *outp = s;
}

// ---------------------------------------------------------------------------
__global__ void k_compact() {
    int i = blockIdx.x * blockDim.x + threadIdx.x;
    if (i >= N_EMB) return;
    if (g_flag[i]) {
        int slot = atomicAdd(&g_cnt, 1);
        g_list[slot] = i;
        g_inv[i] = slot;
    }
}

// ---------------------------------------------------------------------------
__device__ __forceinline__ void ldmatrix_x4(uint32_t* d, uint32_t addr) {
    asm volatile("ldmatrix.sync.aligned.m8n8.x4.shared.b16 {%0,%1,%2,%3}, [%4];"
                 : "=r"(d[0]), "=r"(d[1]), "=r"(d[2]), "=r"(d[3]) : "r"(addr));
}
// f16-accumulator HMMA: D,C are 2x f16x2 regs.
__device__ __forceinline__ void mma16816h(uint32_t& d0, uint32_t& d1,
                                          const uint32_t* a,
                                          uint32_t b0, uint32_t b1) {
    asm volatile("mma.sync.aligned.m16n8k16.row.col.f16.f16.f16.f16 "
                 "{%0,%1}, {%2,%3,%4,%5}, {%6,%7}, {%0,%1};"
                 : "+r"(d0), "+r"(d1)
                 : "r"(a[0]), "r"(a[1]), "r"(a[2]), "r"(a[3]), "r"(b0), "r"(b1));
}
__device__ __forceinline__ uint32_t smem_u32(const void* p) {
    uint32_t a;
    asm("{ .reg .u64 t; cvta.to.shared.u64 t, %1; cvt.u32.u64 %0, t; }"
        : "=r"(a) : "l"(p));
    return a;
}
__device__ __forceinline__ void cp_async16(uint32_t smem_addr, const void* gptr) {
    asm volatile("cp.async.cg.shared.global [%0], [%1], 16;"
                 :: "r"(smem_addr), "l"(gptr));
}
__device__ __forceinline__ void cp_commit() {
    asm volatile("cp.async.commit_group;");
}
template <int N>
__device__ __forceinline__ void cp_wait() {
    asm volatile("cp.async.wait_group %0;" :: "n"(N) : "memory");
}

// ---------------------------------------------------------------------------
// Fused gathered fp16 MMA GEMM (f16 accumulate) + online LSE over distinct
// anchors. Ragged NSPLIT=11 single-wave grid, 3-stage cp.async ring.
__global__ __launch_bounds__(256, 2) void k_lse(int nPos) {
    int cnt = g_cnt;
    int m0 = blockIdx.x * BM;
    if (m0 >= cnt) return;

    int y = blockIdx.y;
    int c_start = (y < 9) ? 6 * y : 54 + 5 * (y - 9);
    int c_cnt   = (y < 9) ? 6 : 5;
    int nslabs  = c_cnt * 8;

    extern __shared__ __align__(16) char dsm[];
    uint32_t a_base = smem_u32(dsm);
    uint32_t b_base = a_base + NSTAGE * A_STAGE;

    __shared__ int arow[BM];
    __shared__ float pm_s[2][BM];
    __shared__ float ps_s[2][BM];

    int tid = threadIdx.x;
    int warp = tid >> 5;
    int lane = tid & 31;
    int warpm = warp >> 1;
    int warpn = warp & 1;

    if (tid < BM) {
        int p = m0 + tid;
        if (p >= cnt) p = cnt - 1;
        arow[tid] = g_list[p];
    }
    __syncthreads();

    int lr0 = tid >> 3;
    int lci = tid & 7;
    uint32_t dst0 = ((uint32_t)lr0 * 128u + (uint32_t)lci * 16u)
                  ^ ((uint32_t)(lr0 & 7) << 4);

    auto load_slab = [&](int t) {
        int c = c_start + (t >> 3);
        int kp = t & 7;
        int k0 = kp * BK;
        int n0 = c * BN;
        uint32_t Ab = a_base + (t % NSTAGE) * A_STAGE + dst0;
        uint32_t Bb = b_base + (t % NSTAGE) * B_STAGE + dst0;
        const __half* bsrc = g_eh + (size_t)(n0 + lr0) * D + k0 + lci * 8;
#pragma unroll
        for (int it = 0; it < 4; it++) {
            cp_async16(Ab + it * 4096u,
                       g_eh + (size_t)arow[it * 32 + lr0] * D + k0 + lci * 8);
            cp_async16(Bb + it * 4096u, bsrc + (size_t)(it * 32) * D);
        }
        cp_commit();
    };

    // ldmatrix bases un-swizzled; swizzle XOR applied after adding kk offset.
    uint32_t swz = ((uint32_t)(lane & 7)) << 4;
    uint32_t baseA0 = (uint32_t)(warpm * 32 + (lane & 15)) * 128u
                    + (uint32_t)(lane >> 4) * 16u;
    uint32_t baseA1 = baseA0 + 16u * 128u;
    uint32_t baseB0 = (uint32_t)(warpn * 64 + (lane & 15)) * 128u
                    + (uint32_t)(lane >> 4) * 16u;

    float rmv[4];
    float rsv[4];
#pragma unroll
    for (int u = 0; u < 4; u++) { rmv[u] = -1e30f; rsv[u] = 0.0f; }

    // f16x2 accumulators: hacc[(mi*8 + j)*2 + h]; h=0 rows lane/4, h=1 rows +8
    uint32_t hacc[32];
#pragma unroll
    for (int q = 0; q < 32; q++) hacc[q] = 0u;

    load_slab(0);
    load_slab(1);

    for (int t = 0; t < nslabs; t++) {
        if (t < nslabs - 1) cp_wait<1>(); else cp_wait<0>();
        __syncthreads();
        if (t + 2 < nslabs) load_slab(t + 2);

        uint32_t Ab = a_base + (t % NSTAGE) * A_STAGE;
        uint32_t Bb = b_base + (t % NSTAGE) * B_STAGE;
#pragma unroll
        for (int kk = 0; kk < 4; kk++) {
            uint32_t kof = (uint32_t)kk * 32u;
            uint32_t afr0[4];
            uint32_t afr1[4];
            uint32_t bfr[4][4];
            ldmatrix_x4(afr0, Ab + ((baseA0 + kof) ^ swz));
            ldmatrix_x4(afr1, Ab + ((baseA1 + kof) ^ swz));
#pragma unroll
            for (int g = 0; g < 4; g++)
                ldmatrix_x4(bfr[g], Bb + ((baseB0 + (uint32_t)g * 2048u + kof) ^ swz));
#pragma unroll
            for (int g = 0; g < 4; g++) {
                mma16816h(hacc[(2 * g + 0) * 2 + 0], hacc[(2 * g + 0) * 2 + 1],
                          afr0, bfr[g][0], bfr[g][2]);
                mma16816h(hacc[(2 * g + 1) * 2 + 0], hacc[(2 * g + 1) * 2 + 1],
                          afr0, bfr[g][1], bfr[g][3]);
                mma16816h(hacc[(8 + 2 * g + 0) * 2 + 0], hacc[(8 + 2 * g + 0) * 2 + 1],
                          afr1, bfr[g][0], bfr[g][2]);
                mma16816h(hacc[(8 + 2 * g + 1) * 2 + 0], hacc[(8 + 2 * g + 1) * 2 + 1],
                          afr1, bfr[g][1], bfr[g][3]);
            }
        }

        if ((t & 7) == 7) {
            // epilogue: online LSE over this 128-col chunk
#pragma unroll
            for (int u = 0; u < 4; u++) {
                int mi = u >> 1;
                int h = u & 1;
                float vals[16];
#pragma unroll
                for (int j = 0; j < 8; j++) {
                    __half2 hv = *reinterpret_cast<__half2*>(&hacc[(mi * 8 + j) * 2 + h]);
                    float2 fv = __half22float2(hv);
                    vals[2 * j + 0] = fv.x * INV_T;
                    vals[2 * j + 1] = fv.y * INV_T;
                }
                float vmax = vals[0];
#pragma unroll
                for (int q = 1; q < 16; q++) vmax = fmaxf(vmax, vals[q]);
                float vsum = 0.0f;
#pragma unroll
                for (int q = 0; q < 16; q++) vsum += __expf(vals[q] - vmax);
#pragma unroll
                for (int o = 1; o < 4; o <<= 1) {
                    float mo = __shfl_xor_sync(0xffffffffu, vmax, o);
                    float so = __shfl_xor_sync(0xffffffffu, vsum, o);
                    float nm = fmaxf(vmax, mo);
                    vsum = vsum * __expf(vmax - nm) + so * __expf(mo - nm);
                    vmax = nm;
                }
                if ((lane & 3) == 0) {
                    int lrr = warpm * 32 + mi * 16 + h * 8 + (lane >> 2);
                    pm_s[warpn][lrr] = vmax;
                    ps_s[warpn][lrr] = vsum;
                }
            }
            __syncthreads();
            if (warpn == 0) {
#pragma unroll
                for (int u = 0; u < 4; u++) {
                    int mi = u >> 1;
                    int h = u & 1;
                    int lrr = warpm * 32 + mi * 16 + h * 8 + (lane >> 2);
                    float m = pm_s[0][lrr];
                    float s = ps_s[0][lrr];
                    float mo = pm_s[1][lrr];
                    float so = ps_s[1][lrr];
                    float nm = fmaxf(m, mo);
                    s = s * __expf(m - nm) + so * __expf(mo - nm);
                    m = nm;
                    float nr = fmaxf(rmv[u], m);
                    rsv[u] = rsv[u] * __expf(rmv[u] - nr) + s * __expf(m - nr);
                    rmv[u] = nr;
                }
            }
            __syncthreads();
#pragma unroll
            for (int q = 0; q < 32; q++) hacc[q] = 0u;
        }
    }

    if (warpn == 0 && (lane & 3) == 0) {
#pragma unroll
        for (int u = 0; u < 4; u++) {
            int mi = u >> 1;
            int h = u & 1;
            int slot = m0 + warpm * 32 + mi * 16 + h * 8 + (lane >> 2);
            if (slot < cnt) {
                g_pm[y * P_MAX + slot] = rmv[u];
                g_ps[y * P_MAX + slot] = rsv[u];
            }
        }
    }
}

// ---------------------------------------------------------------------------
__global__ void k_fin1(const int* __restrict__ pa, int nPos, int nNeg) {
    int b = blockIdx.x;
    int t = threadIdx.x;
    __shared__ float r0[128];
    __shared__ float r1[128];
    if (b < 32) {
        int p = b * 128 + t;
        float lv = 0.0f;
        float pv = 0.0f;
        if (p < nPos) {
            int slot = g_inv[pa[p]];
            float m = -1e30f;
            float s = 0.0f;
#pragma unroll
            for (int k = 0; k < NPART; k++) {
                float mk = g_pm[k * P_MAX + slot];
                float sk = g_ps[k * P_MAX + slot];
                float nm = fmaxf(m, mk);
                s = s * __expf(m - nm) + sk * __expf(mk - nm);
                m = nm;
            }
            float d = g_posdot[p];
            lv = m + logf(s) - d * INV_T;
            pv = d;
        }
        r0[t] = lv;
        r1[t] = pv;
        __syncthreads();
        for (int o = 64; o; o >>= 1) {
            if (t < o) { r0[t] += r0[t + o]; r1[t] += r1[t + o]; }
            __syncthreads();
        }
        if (t == 0) { g_part_l[b] = r0[0]; g_part_p[b] = r1[0]; }
    } else {
        int nb = b - 32;
        float nv = 0.0f;
#pragma unroll
        for (int i = 0; i < 4; i++) {
            int idx = nb * 512 + i * 128 + t;
            if (idx < nNeg) nv += g_negdot[idx];
        }
        r0[t] = nv;
        __syncthreads();
        for (int o = 64; o; o >>= 1) {
            if (t < o) r0[t] += r0[t + o];
            __syncthreads();
        }
        if (t == 0) g_part_n[nb] = r0[0];
    }
}

__global__ void k_fin2(float* __restrict__ outp, int nPos, int nNeg, int out_size) {
    int t = threadIdx.x;
    float lv = (t < 32) ? g_part_l[t] : 0.0f;
    float pv = (t < 32) ? g_part_p[t] : 0.0f;
    float nv = (t < 32) ? g_part_n[t] : 0.0f;
#pragma unroll
    for (int o = 16; o; o >>= 1) {
        lv += __shfl_xor_sync(0xffffffffu, lv, o);
        pv += __shfl_xor_sync(0xffffffffu, pv, o);
        nv += __shfl_xor_sync(0xffffffffu, nv, o);
    }
    if (t == 0) {
        if (out_size > 0) outp[0] = lv / (float)nPos;
        if (out_size > 1) outp[1] = pv / (float)nPos;
        if (out_size > 2) outp[2] = nv / (float)nNeg;
    }
}

// ---------------------------------------------------------------------------
extern "C" void kernel_launch(void* const* d_in, const int* in_sizes, int n_in,
                              void* d_out, int out_size) {
    const float* emb = (const float*)d_in[0];
    const int* pa = (const int*)d_in[1];
    const int* pt = (const int*)d_in[2];
    const int* na = (const int*)d_in[3];
    const int* nt = (const int*)d_in[4];
    int nPos = in_sizes[1];
    int nNeg = in_sizes[3];

    cudaFuncSetAttribute(k_lse, cudaFuncAttributeMaxDynamicSharedMemorySize, SMEM_DYN);

    k_normalize<<<N_EMB, 128>>>(emb);

    int pairs = nPos + nNeg;
    int pblocks = (pairs * 32 + 255) / 256;
    k_pairdot<<<pblocks, 256>>>(pa, pt, na, nt, nPos, nNeg);

    k_compact<<<N_EMB / 256, 256>>>();

    dim3 grid((P_MAX + BM - 1) / BM, NSPLIT);
    k_lse<<<grid, 256, SMEM_DYN>>>(nPos);

    k_fin1<<<64, 128>>>(pa, nPos, nNeg);
    k_fin2<<<1, 32>>>((float*)d_out, nPos, nNeg, out_size);
}